// round 14
// baseline (speedup 1.0000x reference)
#include <cuda_runtime.h>
#include <cstdint>
#include <float.h>

// Sparsemax, one 256-thread block per row. Row fetched via 4 chunked TMA
// bulk copies (8 KB each, own mbarrier); pass A scans chunk c while chunks
// c+1..3 are still in flight -> per-block exposed TMA latency is the first
// chunk only. All compute passes read smem (29-cyc LDS).
//
// thresh = rowmax - 1 (tau >= thresh always) -> support C = {x > thresh},
// |C| ~ 6 for Gaussian rows. Gather gated by per-thread pass-A max (exact).
// Exact Newton/Michelot on C, run redundantly by every warp (no broadcast
// barrier). Guarded block-Michelot fallback preserves correctness for any
// input.

#define COLS 8192
#define C4   (COLS / 4)
#define T    256
#define VPT  (C4 / T)              // 8 float4 per thread
#define NCHUNK 4
#define CHUNK_F4 (C4 / NCHUNK)     // 512 float4 per chunk
#define VPC  (CHUNK_F4 / T)        // 2 float4 per thread per chunk
#define CHUNK_BYTES (COLS * 4 / NCHUNK)   // 8192 bytes
#define CAP  1024

__device__ __forceinline__ uint32_t s2u(const void* p) {
    return (uint32_t)__cvta_generic_to_shared(p);
}
__device__ __forceinline__ void mbar_wait0(uint32_t a) {
    uint32_t done;
    asm volatile(
        "{\n\t.reg .pred p;\n\t"
        "mbarrier.try_wait.parity.acquire.cta.shared::cta.b64 p, [%1], 0;\n\t"
        "selp.b32 %0, 1, 0, p;\n\t}"
        : "=r"(done) : "r"(a) : "memory");
    if (!done) {
        asm volatile(
            "{\n\t.reg .pred P1;\n\t"
            "W_%=:\n\t"
            "mbarrier.try_wait.parity.acquire.cta.shared::cta.b64 P1, [%0], 0, 0x989680;\n\t"
            "@P1 bra.uni D_%=;\n\t"
            "bra.uni W_%=;\n\t"
            "D_%=:\n\t}"
            :: "r"(a) : "memory");
    }
}

__global__ __launch_bounds__(T)
void sparsemax_tma2(const float* __restrict__ x, float* __restrict__ out, int rows)
{
    __shared__ __align__(128) float s_buf[COLS];      // 32 KB row buffer
    __shared__ unsigned long long s_mbar[NCHUNK];
    __shared__ float s_red[T / 32];
    __shared__ float s_cand[CAP];
    __shared__ int   s_cnt;
    __shared__ float s_max;
    __shared__ float s_tau;
    __shared__ int   s_done;
    __shared__ float s_fb[2 * (T / 32)];

    const int tid  = threadIdx.x;
    const int lane = tid & 31;
    const int wid  = tid >> 5;
    const long long row = blockIdx.x;
    if (row >= rows) return;

    if (tid == 0) {
        s_cnt = 0;
#pragma unroll
        for (int c = 0; c < NCHUNK; ++c)
            asm volatile("mbarrier.init.shared.b64 [%0], 1;"
                         :: "r"(s2u(&s_mbar[c])) : "memory");
    }
    __syncthreads();

    // ---- issue all 4 chunked TMA copies up front ----
    if (tid == 0) {
        const char* src = (const char*)(x + row * COLS);
#pragma unroll
        for (int c = 0; c < NCHUNK; ++c) {
            uint32_t mb = s2u(&s_mbar[c]);
            asm volatile("mbarrier.arrive.expect_tx.shared.b64 _, [%0], %1;"
                         :: "r"(mb), "r"((uint32_t)CHUNK_BYTES) : "memory");
            asm volatile(
                "cp.async.bulk.shared::cta.global.mbarrier::complete_tx::bytes [%0], [%1], %2, [%3];"
                :: "r"(s2u(s_buf) + c * CHUNK_BYTES),
                   "l"(src + (size_t)c * CHUNK_BYTES),
                   "r"((uint32_t)CHUNK_BYTES), "r"(mb) : "memory");
        }
    }

    const float4* __restrict__ b4 = reinterpret_cast<const float4*>(s_buf);

    // ---- pass A: per-chunk wait + scan (pipelined against TMA arrival) ----
    float m0 = -FLT_MAX, m1 = -FLT_MAX, m2 = -FLT_MAX, m3 = -FLT_MAX;
#pragma unroll
    for (int c = 0; c < NCHUNK; ++c) {
        mbar_wait0(s2u(&s_mbar[c]));
#pragma unroll
        for (int i = 0; i < VPC; ++i) {
            float4 v = b4[c * CHUNK_F4 + tid + i * T];
            m0 = fmaxf(m0, v.x);
            m1 = fmaxf(m1, v.y);
            m2 = fmaxf(m2, v.z);
            m3 = fmaxf(m3, v.w);
        }
    }
    const float tmax = fmaxf(fmaxf(m0, m1), fmaxf(m2, m3));

    // ---- block max ----
    float m = tmax;
#pragma unroll
    for (int o = 16; o > 0; o >>= 1) m = fmaxf(m, __shfl_xor_sync(0xffffffffu, m, o));
    if (lane == 0) s_red[wid] = m;
    __syncthreads();
    if (wid == 0) {
        float t = (lane < T / 32) ? s_red[lane] : -FLT_MAX;
#pragma unroll
        for (int o = 4; o > 0; o >>= 1) t = fmaxf(t, __shfl_xor_sync(0xffffffffu, t, o));
        if (lane == 0) s_max = t;
    }
    __syncthreads();
    const float thresh = s_max - 1.0f;                 // tau >= thresh always

    // ---- gather: only threads whose own max clears thresh re-scan smem ----
    if (tmax > thresh) {
#pragma unroll 1
        for (int i = 0; i < VPT; ++i) {
            float4 v = b4[tid + i * T];
            if (v.x > thresh) { int q = atomicAdd(&s_cnt, 1); if (q < CAP) s_cand[q] = v.x; }
            if (v.y > thresh) { int q = atomicAdd(&s_cnt, 1); if (q < CAP) s_cand[q] = v.y; }
            if (v.z > thresh) { int q = atomicAdd(&s_cnt, 1); if (q < CAP) s_cand[q] = v.z; }
            if (v.w > thresh) { int q = atomicAdd(&s_cnt, 1); if (q < CAP) s_cand[q] = v.w; }
        }
    }
    __syncthreads();
    const int cnt = s_cnt;

    float tau;
    if (cnt <= CAP) {
        // ---- exact Newton/Michelot on tiny candidate set, ALL warps
        //      redundantly (same data -> same tau; no broadcast barrier) ----
        float tt = thresh;
#pragma unroll 1
        for (int it = 0; it < 64; ++it) {
            float s = 0.0f, k = 0.0f;
            for (int i = lane; i < cnt; i += 32) {
                float c = s_cand[i];
                if (c > tt) { s += c; k += 1.0f; }
            }
#pragma unroll
            for (int o = 16; o > 0; o >>= 1) {
                s += __shfl_xor_sync(0xffffffffu, s, o);
                k += __shfl_xor_sync(0xffffffffu, k, o);
            }
            if (k < 0.5f) break;              // safety (cannot happen in theory)
            float nt = (s - 1.0f) / k;
            if (nt == tt) break;              // exact fixed point
            tt = nt;
        }
        tau = tt;
    } else {
        // ---- pathological fallback: block Michelot over smem row ----
        float tt = thresh;
#pragma unroll 1
        for (int it = 0; it < 64; ++it) {
            float s = 0.0f, k = 0.0f;
#pragma unroll 1
            for (int i = 0; i < VPT; ++i) {
                float4 v = b4[tid + i * T];
                if (v.x > tt) { s += v.x; k += 1.0f; }
                if (v.y > tt) { s += v.y; k += 1.0f; }
                if (v.z > tt) { s += v.z; k += 1.0f; }
                if (v.w > tt) { s += v.w; k += 1.0f; }
            }
#pragma unroll
            for (int o = 16; o > 0; o >>= 1) {
                s += __shfl_xor_sync(0xffffffffu, s, o);
                k += __shfl_xor_sync(0xffffffffu, k, o);
            }
            if (lane == 0) { s_fb[2 * wid] = s; s_fb[2 * wid + 1] = k; }
            __syncthreads();
            if (tid == 0) {
                float Sx = 0.0f, K = 0.0f;
                for (int w = 0; w < T / 32; ++w) { Sx += s_fb[2 * w]; K += s_fb[2 * w + 1]; }
                float nt = (K < 0.5f) ? tt : (Sx - 1.0f) / K;
                s_done = (nt == tt) || (K < 0.5f);
                s_tau  = nt;
            }
            __syncthreads();
            tt = s_tau;
            if (s_done) break;
        }
        tau = tt;
    }

    // ---- pass C: read smem, emit output (streaming stores) ----
    float4* __restrict__ yr = reinterpret_cast<float4*>(out + row * COLS);
#pragma unroll
    for (int i = 0; i < VPT; ++i) {
        float4 v = b4[tid + i * T];
        float4 r;
        r.x = fmaxf(v.x - tau, 0.0f);
        r.y = fmaxf(v.y - tau, 0.0f);
        r.z = fmaxf(v.z - tau, 0.0f);
        r.w = fmaxf(v.w - tau, 0.0f);
        __stcs(yr + tid + i * T, r);
    }
}

extern "C" void kernel_launch(void* const* d_in, const int* in_sizes, int n_in,
                              void* d_out, int out_size)
{
    const float* x = (const float*)d_in[0];
    float* out     = (float*)d_out;
    const int rows = in_sizes[0] / COLS;
    sparsemax_tma2<<<rows, T>>>(x, out, rows);
}

// round 15
// speedup vs baseline: 1.0870x; 1.0870x over previous
#include <cuda_runtime.h>
#include <cstdint>
#include <float.h>

// Sparsemax, one 256-thread block per row. Row in via ONE TMA bulk copy
// (R13 config -- chunking regressed), row out via ONE TMA bulk store:
// pass C computes max(x - tau, 0) back into the smem buffer in place, then
// a single cp.async.bulk shared->global drains it at engine rate. Warps
// never issue global loads or stores; all compute reads/writes are smem.
//
// thresh = rowmax - 1 (tau >= thresh always) -> support C = {x > thresh},
// |C| ~ 6 for Gaussian rows. Gather gated by per-thread pass-A max (exact).
// Exact Newton/Michelot on C, run redundantly by every warp (no broadcast
// barrier). Guarded block-Michelot fallback preserves correctness.

#define COLS 8192
#define C4   (COLS / 4)
#define T    256
#define VPT  (C4 / T)             // 8 float4 per thread
#define CAP  1024
#define ROW_BYTES (COLS * 4)

__device__ __forceinline__ uint32_t s2u(const void* p) {
    return (uint32_t)__cvta_generic_to_shared(p);
}

__global__ __launch_bounds__(T)
void sparsemax_tmaio(const float* __restrict__ x, float* __restrict__ out, int rows)
{
    __shared__ __align__(128) float s_buf[COLS];      // 32 KB row buffer
    __shared__ unsigned long long s_mbar;
    __shared__ float s_red[T / 32];
    __shared__ float s_cand[CAP];
    __shared__ int   s_cnt;
    __shared__ float s_max;
    __shared__ float s_tau;
    __shared__ int   s_done;
    __shared__ float s_fb[2 * (T / 32)];

    const int tid  = threadIdx.x;
    const int lane = tid & 31;
    const int wid  = tid >> 5;
    const long long row = blockIdx.x;
    if (row >= rows) return;

    const uint32_t mb = s2u(&s_mbar);

    if (tid == 0) {
        s_cnt = 0;
        asm volatile("mbarrier.init.shared.b64 [%0], 1;" :: "r"(mb) : "memory");
    }
    __syncthreads();

    // ---- one TMA bulk copy in: DRAM -> smem ----
    if (tid == 0) {
        asm volatile("mbarrier.arrive.expect_tx.shared.b64 _, [%0], %1;"
                     :: "r"(mb), "r"((uint32_t)ROW_BYTES) : "memory");
        asm volatile(
            "cp.async.bulk.shared::cta.global.mbarrier::complete_tx::bytes [%0], [%1], %2, [%3];"
            :: "r"(s2u(s_buf)), "l"((const void*)(x + row * COLS)),
               "r"((uint32_t)ROW_BYTES), "r"(mb) : "memory");
    }
    {   // all threads wait for arrival
        uint32_t done;
        asm volatile(
            "{\n\t.reg .pred p;\n\t"
            "mbarrier.try_wait.parity.acquire.cta.shared::cta.b64 p, [%1], 0;\n\t"
            "selp.b32 %0, 1, 0, p;\n\t}"
            : "=r"(done) : "r"(mb) : "memory");
        if (!done) {
            asm volatile(
                "{\n\t.reg .pred P1;\n\t"
                "W_%=:\n\t"
                "mbarrier.try_wait.parity.acquire.cta.shared::cta.b64 P1, [%0], 0, 0x989680;\n\t"
                "@P1 bra.uni D_%=;\n\t"
                "bra.uni W_%=;\n\t"
                "D_%=:\n\t}"
                :: "r"(mb) : "memory");
        }
    }

    float4* __restrict__ b4 = reinterpret_cast<float4*>(s_buf);

    // ---- pass A: smem scan, per-thread max (4 independent chains) ----
    float m0 = -FLT_MAX, m1 = -FLT_MAX, m2 = -FLT_MAX, m3 = -FLT_MAX;
#pragma unroll
    for (int i = 0; i < VPT; ++i) {
        float4 v = b4[tid + i * T];
        m0 = fmaxf(m0, v.x);
        m1 = fmaxf(m1, v.y);
        m2 = fmaxf(m2, v.z);
        m3 = fmaxf(m3, v.w);
    }
    const float tmax = fmaxf(fmaxf(m0, m1), fmaxf(m2, m3));

    // ---- block max ----
    float m = tmax;
#pragma unroll
    for (int o = 16; o > 0; o >>= 1) m = fmaxf(m, __shfl_xor_sync(0xffffffffu, m, o));
    if (lane == 0) s_red[wid] = m;
    __syncthreads();
    if (wid == 0) {
        float t = (lane < T / 32) ? s_red[lane] : -FLT_MAX;
#pragma unroll
        for (int o = 4; o > 0; o >>= 1) t = fmaxf(t, __shfl_xor_sync(0xffffffffu, t, o));
        if (lane == 0) s_max = t;
    }
    __syncthreads();
    const float thresh = s_max - 1.0f;                 // tau >= thresh always

    // ---- gather: only threads whose own max clears thresh re-scan smem ----
    if (tmax > thresh) {
#pragma unroll 1
        for (int i = 0; i < VPT; ++i) {
            float4 v = b4[tid + i * T];
            if (v.x > thresh) { int q = atomicAdd(&s_cnt, 1); if (q < CAP) s_cand[q] = v.x; }
            if (v.y > thresh) { int q = atomicAdd(&s_cnt, 1); if (q < CAP) s_cand[q] = v.y; }
            if (v.z > thresh) { int q = atomicAdd(&s_cnt, 1); if (q < CAP) s_cand[q] = v.z; }
            if (v.w > thresh) { int q = atomicAdd(&s_cnt, 1); if (q < CAP) s_cand[q] = v.w; }
        }
    }
    __syncthreads();
    const int cnt = s_cnt;

    float tau;
    if (cnt <= CAP) {
        // ---- exact Newton/Michelot on tiny candidate set, ALL warps
        //      redundantly (same data -> same tau; no broadcast barrier) ----
        float tt = thresh;
#pragma unroll 1
        for (int it = 0; it < 64; ++it) {
            float s = 0.0f, k = 0.0f;
            for (int i = lane; i < cnt; i += 32) {
                float c = s_cand[i];
                if (c > tt) { s += c; k += 1.0f; }
            }
#pragma unroll
            for (int o = 16; o > 0; o >>= 1) {
                s += __shfl_xor_sync(0xffffffffu, s, o);
                k += __shfl_xor_sync(0xffffffffu, k, o);
            }
            if (k < 0.5f) break;              // safety (cannot happen in theory)
            float nt = (s - 1.0f) / k;
            if (nt == tt) break;              // exact fixed point
            tt = nt;
        }
        tau = tt;
    } else {
        // ---- pathological fallback: block Michelot over smem row ----
        float tt = thresh;
#pragma unroll 1
        for (int it = 0; it < 64; ++it) {
            float s = 0.0f, k = 0.0f;
#pragma unroll 1
            for (int i = 0; i < VPT; ++i) {
                float4 v = b4[tid + i * T];
                if (v.x > tt) { s += v.x; k += 1.0f; }
                if (v.y > tt) { s += v.y; k += 1.0f; }
                if (v.z > tt) { s += v.z; k += 1.0f; }
                if (v.w > tt) { s += v.w; k += 1.0f; }
            }
#pragma unroll
            for (int o = 16; o > 0; o >>= 1) {
                s += __shfl_xor_sync(0xffffffffu, s, o);
                k += __shfl_xor_sync(0xffffffffu, k, o);
            }
            if (lane == 0) { s_fb[2 * wid] = s; s_fb[2 * wid + 1] = k; }
            __syncthreads();
            if (tid == 0) {
                float Sx = 0.0f, K = 0.0f;
                for (int w = 0; w < T / 32; ++w) { Sx += s_fb[2 * w]; K += s_fb[2 * w + 1]; }
                float nt = (K < 0.5f) ? tt : (Sx - 1.0f) / K;
                s_done = (nt == tt) || (K < 0.5f);
                s_tau  = nt;
            }
            __syncthreads();
            tt = s_tau;
            if (s_done) break;
        }
        tau = tt;
    }

    // ---- pass C: compute into smem IN PLACE (thread-private slots) ----
#pragma unroll
    for (int i = 0; i < VPT; ++i) {
        float4 v = b4[tid + i * T];
        float4 r;
        r.x = fmaxf(v.x - tau, 0.0f);
        r.y = fmaxf(v.y - tau, 0.0f);
        r.z = fmaxf(v.z - tau, 0.0f);
        r.w = fmaxf(v.w - tau, 0.0f);
        b4[tid + i * T] = r;
    }
    __syncthreads();

    // ---- one TMA bulk store out: smem -> DRAM (engine-driven) ----
    if (tid == 0) {
        asm volatile("fence.proxy.async.shared::cta;" ::: "memory");
        asm volatile(
            "cp.async.bulk.global.shared::cta.bulk_group [%0], [%1], %2;"
            :: "l"((void*)(out + row * COLS)), "r"(s2u(s_buf)),
               "r"((uint32_t)ROW_BYTES) : "memory");
        asm volatile("cp.async.bulk.commit_group;" ::: "memory");
        asm volatile("cp.async.bulk.wait_group 0;" ::: "memory");
    }
    __syncthreads();   // keep smem alive until the bulk store has read it
}

extern "C" void kernel_launch(void* const* d_in, const int* in_sizes, int n_in,
                              void* d_out, int out_size)
{
    const float* x = (const float*)d_in[0];
    float* out     = (float*)d_out;
    const int rows = in_sizes[0] / COLS;
    sparsemax_tmaio<<<rows, T>>>(x, out, rows);
}